// round 1
// baseline (speedup 1.0000x reference)
#include <cuda_runtime.h>
#include <cuda_bf16.h>

#define BB 2048
#define TT 1024
#define H  32
#define NA 4

__global__ __launch_bounds__(256, 1) void vanilla_rnn_kernel(
    const float* __restrict__ act,   // [B, T, 4]
    const float* __restrict__ rew,   // [B, T, 1]
    const float* __restrict__ W_ih,  // [32, 5]
    const float* __restrict__ W_hh,  // [32, 32]
    const float* __restrict__ b_ih,  // [32]
    const float* __restrict__ b_hh,  // [32]
    const float* __restrict__ W_ro,  // [4, 32]
    const float* __restrict__ b_ro,  // [4]
    float* __restrict__ out)         // [B*T*4 logits][B*32 h_T]
{
    const int warp = (blockIdx.x * blockDim.x + threadIdx.x) >> 5;
    const int lane = threadIdx.x & 31;
    if (warp >= BB) return;
    const int b = warp;

    // Per-lane weights: lane i owns row i of W_hh (and W_ro for lanes < 4).
    float whh[H];
#pragma unroll
    for (int j = 0; j < H; j++) whh[j] = W_hh[lane * H + j];
    float wih[5];
#pragma unroll
    for (int k = 0; k < 5; k++) wih[k] = W_ih[lane * 5 + k];
    float wro[H];
#pragma unroll
    for (int j = 0; j < H; j++) wro[j] = (lane < NA) ? W_ro[lane * H + j] : 0.0f;
    const float bias = b_ih[lane] + b_hh[lane];
    const float bro  = (lane < NA) ? b_ro[lane] : 0.0f;

    const float4* actv = reinterpret_cast<const float4*>(act) + (size_t)b * TT;
    const float*  rewp = rew + (size_t)b * TT;
    float* logits = out + (size_t)b * TT * NA;
    float* hTout  = out + (size_t)BB * TT * NA + (size_t)b * H;

    float h = 0.0f;  // h_{t-1}; h_{-1} = 0 (matches reference h0 = zeros)

    for (int t = 0; t < TT; t++) {
        // Uniform (warp-broadcast) input loads for this step.
        const float4 a = __ldg(actv + t);
        const float  r = __ldg(rewp + t);
        const float xp = fmaf(a.x, wih[0],
                         fmaf(a.y, wih[1],
                         fmaf(a.z, wih[2],
                         fmaf(a.w, wih[3],
                         fmaf(r,   wih[4], bias)))));

        // Broadcast h_{t-1} across the warp once; feed BOTH the recurrence
        // (W_hh row) and the readout (W_ro row, lanes 0..3) from it.
        float s0 = 0.f, s1 = 0.f, s2 = 0.f, s3 = 0.f;
        float l0 = 0.f, l1 = 0.f;
#pragma unroll
        for (int j = 0; j < H; j += 4) {
            const float h0 = __shfl_sync(0xffffffffu, h, j + 0);
            const float h1 = __shfl_sync(0xffffffffu, h, j + 1);
            const float h2 = __shfl_sync(0xffffffffu, h, j + 2);
            const float h3 = __shfl_sync(0xffffffffu, h, j + 3);
            s0 = fmaf(whh[j + 0], h0, s0);
            s1 = fmaf(whh[j + 1], h1, s1);
            s2 = fmaf(whh[j + 2], h2, s2);
            s3 = fmaf(whh[j + 3], h3, s3);
            l0 = fmaf(wro[j + 0], h0, l0);
            l1 = fmaf(wro[j + 1], h1, l1);
            l0 = fmaf(wro[j + 2], h2, l0);
            l1 = fmaf(wro[j + 3], h3, l1);
        }
        // The broadcast carried h_{t-1}: emit logits for step t-1.
        if (t > 0 && lane < NA)
            logits[(size_t)(t - 1) * NA + lane] = l0 + l1 + bro;

        h = tanhf(xp + (s0 + s1) + (s2 + s3));
    }

    // Tail: logits for t = T-1 from the final h.
    {
        float l0 = 0.f, l1 = 0.f;
#pragma unroll
        for (int j = 0; j < H; j += 2) {
            const float h0 = __shfl_sync(0xffffffffu, h, j + 0);
            const float h1 = __shfl_sync(0xffffffffu, h, j + 1);
            l0 = fmaf(wro[j + 0], h0, l0);
            l1 = fmaf(wro[j + 1], h1, l1);
        }
        if (lane < NA)
            logits[(size_t)(TT - 1) * NA + lane] = l0 + l1 + bro;
    }

    hTout[lane] = h;
}

extern "C" void kernel_launch(void* const* d_in, const int* in_sizes, int n_in,
                              void* d_out, int out_size) {
    const float* act  = (const float*)d_in[0];
    const float* rew  = (const float*)d_in[1];
    const float* W_ih = (const float*)d_in[2];
    const float* W_hh = (const float*)d_in[3];
    const float* b_ih = (const float*)d_in[4];
    const float* b_hh = (const float*)d_in[5];
    const float* W_ro = (const float*)d_in[6];
    const float* b_ro = (const float*)d_in[7];
    float* out = (float*)d_out;

    // 2048 warps total: 256 blocks x 256 threads (8 warps/block).
    dim3 grid(BB / 8), block(256);
    vanilla_rnn_kernel<<<grid, block>>>(act, rew, W_ih, W_hh, b_ih, b_hh,
                                        W_ro, b_ro, out);
}

// round 2
// speedup vs baseline: 1.5546x; 1.5546x over previous
#include <cuda_runtime.h>
#include <cstdint>

#define BB 2048
#define TT 1024
#define H  32
#define NA 4

// packed f32x2 FMA (FFMA2) — only reachable via PTX on sm_103a
#define FMA2(d, a, b, c) \
    asm("fma.rn.f32x2 %0, %1, %2, %3;" : "=l"(d) : "l"(a), "l"(b), "l"(c))

__device__ __forceinline__ float2 u2f(unsigned long long v) {
    float2 r;
    asm("mov.b64 {%0, %1}, %2;" : "=f"(r.x), "=f"(r.y) : "l"(v));
    return r;
}

// tanh(x) = 1 - 2/(e^{2x}+1); exact saturation at +/-inf, rel err ~1e-6
__device__ __forceinline__ float fast_tanh(float x) {
    float e;
    asm("ex2.approx.f32 %0, %1;" : "=f"(e) : "f"(x * 2.8853900817779268f));
    float r;
    asm("rcp.approx.f32 %0, %1;" : "=f"(r) : "f"(e + 1.0f));
    return fmaf(-2.0f, r, 1.0f);
}

__global__ __launch_bounds__(32, 1) void vanilla_rnn_kernel(
    const float* __restrict__ act,   // [B, T, 4]
    const float* __restrict__ rew,   // [B, T, 1]
    const float* __restrict__ W_ih,  // [32, 5]
    const float* __restrict__ W_hh,  // [32, 32]
    const float* __restrict__ b_ih,  // [32]
    const float* __restrict__ b_hh,  // [32]
    const float* __restrict__ W_ro,  // [4, 32]
    const float* __restrict__ b_ro,  // [4]
    float* __restrict__ out)         // [B*T*4 logits][B*32 h_T]
{
    const int lane = threadIdx.x;
    const int grp  = lane >> 4;        // which of the 2 rows this warp handles
    const int l16  = lane & 15;
    const int b    = blockIdx.x * 2 + grp;

    // h exchange buffer: double-buffered, row stride 40 floats (160B) so the
    // two rows' 16B lines land on different banks.
    __shared__ __align__(16) float hbuf[2][2][40];

    const int o0 = 2 * l16;            // this lane owns h elements o0, o0+1
    const int o1 = o0 + 1;

    // W_hh rows o0,o1 as packed f32-pairs (lo = even col, matching h pairs)
    unsigned long long wh0[16], wh1[16], wr[16];
    const unsigned long long* whh_u = (const unsigned long long*)W_hh;
    #pragma unroll
    for (int j = 0; j < 16; j++) {
        wh0[j] = whh_u[o0 * 16 + j];
        wh1[j] = whh_u[o1 * 16 + j];
    }
    // W_ro row l16 (lanes 0..3 of each group produce the 4 logits)
    const unsigned long long* wro_u = (const unsigned long long*)W_ro;
    const int rr = (l16 < NA) ? l16 : 0;
    #pragma unroll
    for (int j = 0; j < 16; j++) wr[j] = wro_u[rr * 16 + j];

    float wi0[5], wi1[5];
    #pragma unroll
    for (int k = 0; k < 5; k++) {
        wi0[k] = W_ih[o0 * 5 + k];
        wi1[k] = W_ih[o1 * 5 + k];
    }
    const float bias0 = b_ih[o0] + b_hh[o0];
    const float bias1 = b_ih[o1] + b_hh[o1];
    const float bro   = (l16 < NA) ? b_ro[l16] : 0.0f;

    const float4* actv = (const float4*)act + (size_t)b * TT;
    const float*  rewp = rew + (size_t)b * TT;
    float* logits = out + (size_t)b * TT * NA;
    float* hT     = out + (size_t)BB * TT * NA + (size_t)b * H;

    // h_{-1} = 0 in buffer 0
    *(float2*)&hbuf[0][grp][o0] = make_float2(0.0f, 0.0f);
    __syncwarp();

    #pragma unroll 2
    for (int t = 0; t < TT; t++) {
        const int p  = t & 1;
        const int np = p ^ 1;

        // step inputs (uniform within each 16-lane group; L1-resident lines)
        const float4 a = __ldg(actv + t);
        const float  r = __ldg(rewp + t);

        // read full h_{t-1} for this row: 8x LDS.128 as packed pairs
        unsigned long long hv[16];
        const ulonglong2* hp = (const ulonglong2*)hbuf[p][grp];
        #pragma unroll
        for (int j = 0; j < 8; j++) {
            ulonglong2 q = hp[j];
            hv[2 * j]     = q.x;
            hv[2 * j + 1] = q.y;
        }

        // recurrence dots for the 2 owned outputs + readout (all packed)
        unsigned long long s0a = 0, s0b = 0, s1a = 0, s1b = 0, la = 0, lb = 0;
        #pragma unroll
        for (int j = 0; j < 16; j += 2) {
            FMA2(s0a, wh0[j],     hv[j],     s0a);
            FMA2(s0b, wh0[j + 1], hv[j + 1], s0b);
            FMA2(s1a, wh1[j],     hv[j],     s1a);
            FMA2(s1b, wh1[j + 1], hv[j + 1], s1b);
            FMA2(la,  wr[j],      hv[j],     la);
            FMA2(lb,  wr[j + 1],  hv[j + 1], lb);
        }
        float2 c0a = u2f(s0a), c0b = u2f(s0b);
        float2 c1a = u2f(s1a), c1b = u2f(s1b);
        const float dot0 = (c0a.x + c0a.y) + (c0b.x + c0b.y);
        const float dot1 = (c1a.x + c1a.y) + (c1b.x + c1b.y);

        // readout used h_{t-1} -> these are logits for step t-1
        float2 cla = u2f(la), clb = u2f(lb);
        const float lg = (cla.x + cla.y) + (clb.x + clb.y) + bro;
        if (t > 0 && l16 < NA)
            logits[(size_t)(t - 1) * NA + l16] = lg;

        // input projection for the 2 owned elements
        const float x0 = fmaf(a.x, wi0[0], fmaf(a.y, wi0[1],
                         fmaf(a.z, wi0[2], fmaf(a.w, wi0[3],
                         fmaf(r, wi0[4], bias0)))));
        const float x1 = fmaf(a.x, wi1[0], fmaf(a.y, wi1[1],
                         fmaf(a.z, wi1[2], fmaf(a.w, wi1[3],
                         fmaf(r, wi1[4], bias1)))));

        const float h0 = fast_tanh(x0 + dot0);
        const float h1 = fast_tanh(x1 + dot1);

        *(float2*)&hbuf[np][grp][o0] = make_float2(h0, h1);
        __syncwarp();
    }

    // tail: logits for t = T-1 from h_T (sits in buffer TT&1 == 0)
    {
        unsigned long long la = 0, lb = 0;
        const ulonglong2* hp = (const ulonglong2*)hbuf[0][grp];
        #pragma unroll
        for (int j = 0; j < 8; j++) {
            ulonglong2 q = hp[j];
            FMA2(la, wr[2 * j],     q.x, la);
            FMA2(lb, wr[2 * j + 1], q.y, lb);
        }
        float2 cla = u2f(la), clb = u2f(lb);
        const float lg = (cla.x + cla.y) + (clb.x + clb.y) + bro;
        if (l16 < NA)
            logits[(size_t)(TT - 1) * NA + l16] = lg;
    }

    // final hidden state: this lane owns elements o0, o0+1
    {
        const float2 hfin = *(const float2*)&hbuf[0][grp][o0];
        *(float2*)&hT[o0] = hfin;
    }
}

extern "C" void kernel_launch(void* const* d_in, const int* in_sizes, int n_in,
                              void* d_out, int out_size) {
    const float* act  = (const float*)d_in[0];
    const float* rew  = (const float*)d_in[1];
    const float* W_ih = (const float*)d_in[2];
    const float* W_hh = (const float*)d_in[3];
    const float* b_ih = (const float*)d_in[4];
    const float* b_hh = (const float*)d_in[5];
    const float* W_ro = (const float*)d_in[6];
    const float* b_ro = (const float*)d_in[7];
    float* out = (float*)d_out;

    // 2 rows per warp, 1 warp per block -> 1024 blocks. 1024/148 ~ 7 warps/SM
    // with near-perfect wave balance (136 SMs x 7, 12 SMs x 6).
    vanilla_rnn_kernel<<<BB / 2, 32>>>(act, rew, W_ih, W_hh, b_ih, b_hh,
                                       W_ro, b_ro, out);
}

// round 3
// speedup vs baseline: 1.6468x; 1.0593x over previous
#include <cuda_runtime.h>

#define BB 2048
#define TT 1024
#define H  32
#define NA 4
#define CH 4
#define NCH (TT / CH)

// packed f32x2 ops (sm_103a)
#define FMA2(d, a, b, c) \
    asm("fma.rn.f32x2 %0, %1, %2, %3;" : "=l"(d) : "l"(a), "l"(b), "l"(c))
#define ADD2(d, a, b) \
    asm("add.rn.f32x2 %0, %1, %2;" : "=l"(d) : "l"(a), "l"(b))

static __device__ __forceinline__ unsigned long long f2u(float x, float y) {
    unsigned long long r;
    asm("mov.b64 %0, {%1, %2};" : "=l"(r) : "f"(x), "f"(y));
    return r;
}
static __device__ __forceinline__ float2 u2f(unsigned long long v) {
    float2 r;
    asm("mov.b64 {%0, %1}, %2;" : "=f"(r.x), "=f"(r.y) : "l"(v));
    return r;
}
// zs = (2/ln2)*z already scaled -> tanh(z) = 1 - 2/(e^{2z}+1)
static __device__ __forceinline__ float tanh_scaled(float zs) {
    float e;
    asm("ex2.approx.f32 %0, %1;" : "=f"(e) : "f"(zs));
    float r;
    asm("rcp.approx.f32 %0, %1;" : "=f"(r) : "f"(e + 1.0f));
    return fmaf(-2.0f, r, 1.0f);
}

__global__ __launch_bounds__(32, 1) void vanilla_rnn_kernel(
    const float* __restrict__ act,   // [B, T, 4]
    const float* __restrict__ rew,   // [B, T, 1]
    const float* __restrict__ W_ih,  // [32, 5]
    const float* __restrict__ W_hh,  // [32, 32]
    const float* __restrict__ b_ih,  // [32]
    const float* __restrict__ b_hh,  // [32]
    const float* __restrict__ W_ro,  // [4, 32]
    const float* __restrict__ b_ro,  // [4]
    float* __restrict__ out)         // [B*T*4 logits][B*32 h_T]
{
    const int lane = threadIdx.x;
    const int grp  = lane >> 4;   // which of the 2 batch rows in this warp
    const int l16  = lane & 15;
    const int b    = blockIdx.x * 2 + grp;

    __shared__ __align__(16) float hbuf[2][2][40];  // [parity][row][32+pad]

    const int o0 = 2 * l16;       // lane owns h[o0], h[o0+1]
    const int o1 = o0 + 1;

    const float SC = 2.8853900817779268f;  // 2/ln2

    // W_hh rows o0,o1 pre-scaled by SC, packed over the column (j) dimension.
    unsigned long long wh0[16], wh1[16], wr[16];
    const float2* whh2 = (const float2*)W_hh;
    #pragma unroll
    for (int j = 0; j < 16; j++) {
        float2 w0 = whh2[o0 * 16 + j];
        float2 w1 = whh2[o1 * 16 + j];
        wh0[j] = f2u(w0.x * SC, w0.y * SC);
        wh1[j] = f2u(w1.x * SC, w1.y * SC);
    }
    // W_ro row (lanes 0..3 of each 16-lane group are real; rest dummies)
    {
        const float2* wro2 = (const float2*)W_ro;
        const int rr = (l16 < NA) ? l16 : 0;
        #pragma unroll
        for (int j = 0; j < 16; j++) {
            float2 w = wro2[rr * 16 + j];
            wr[j] = f2u(w.x, w.y);
        }
    }
    // input-projection weights, pre-scaled by SC
    float wi0[5], wi1[5];
    #pragma unroll
    for (int k = 0; k < 5; k++) {
        wi0[k] = W_ih[o0 * 5 + k] * SC;
        wi1[k] = W_ih[o1 * 5 + k] * SC;
    }
    const float bias0 = (b_ih[o0] + b_hh[o0]) * SC;
    const float bias1 = (b_ih[o1] + b_hh[o1]) * SC;
    const float bro   = (l16 < NA) ? b_ro[l16] : 0.0f;

    const float4* actv = (const float4*)act + (size_t)b * TT;   // 1 float4/step
    const float4* rewv = (const float4*)(rew + (size_t)b * TT); // 1 float4/chunk
    float* logits = out + (size_t)b * TT * NA;
    float* hT     = out + (size_t)BB * TT * NA + (size_t)b * H;

    // h_{-1} = 0
    *(float2*)&hbuf[0][grp][o0] = make_float2(0.0f, 0.0f);

    // -------- prologue: load + project chunk 0 --------
    float xc0[CH], xc1[CH];
    {
        float4 af[CH];
        #pragma unroll
        for (int i = 0; i < CH; i++) af[i] = __ldg(actv + i);
        const float4 rf = __ldg(rewv);
        const float rs[CH] = {rf.x, rf.y, rf.z, rf.w};
        #pragma unroll
        for (int i = 0; i < CH; i++) {
            xc0[i] = fmaf(af[i].x, wi0[0], fmaf(af[i].y, wi0[1],
                     fmaf(af[i].z, wi0[2], fmaf(af[i].w, wi0[3],
                     fmaf(rs[i], wi0[4], bias0)))));
            xc1[i] = fmaf(af[i].x, wi1[0], fmaf(af[i].y, wi1[1],
                     fmaf(af[i].z, wi1[2], fmaf(af[i].w, wi1[3],
                     fmaf(rs[i], wi1[4], bias1)))));
        }
    }

    #pragma unroll 1
    for (int c = 0; c < NCH; c++) {
        // -------- prefetch next chunk's inputs (consumed after the 4 steps)
        const int cn = (c + 1 < NCH) ? (c + 1) : (NCH - 1);
        float4 naf0 = __ldg(actv + cn * CH + 0);
        float4 naf1 = __ldg(actv + cn * CH + 1);
        float4 naf2 = __ldg(actv + cn * CH + 2);
        float4 naf3 = __ldg(actv + cn * CH + 3);
        float4 nrf  = __ldg(rewv + cn);

        // -------- 4 serial recurrence steps on registered xp --------
        #pragma unroll
        for (int i = 0; i < CH; i++) {
            const int p  = i & 1;           // c*CH is even, so parity = i&1
            const int np = p ^ 1;
            const int t  = c * CH + i;

            __syncwarp();  // prior STS (or init store) visible

            unsigned long long hv[16];
            const ulonglong2* hp = (const ulonglong2*)hbuf[p][grp];
            #pragma unroll
            for (int j = 0; j < 8; j++) {
                ulonglong2 q = hp[j];
                hv[2 * j]     = q.x;
                hv[2 * j + 1] = q.y;
            }

            unsigned long long s0a = f2u(xc0[i], 0.0f), s0b = 0;
            unsigned long long s1a = f2u(xc1[i], 0.0f), s1b = 0;
            unsigned long long la  = 0, lb = 0;
            #pragma unroll
            for (int j = 0; j < 16; j += 2) {
                FMA2(s0a, wh0[j],     hv[j],     s0a);
                FMA2(s0b, wh0[j + 1], hv[j + 1], s0b);
                FMA2(s1a, wh1[j],     hv[j],     s1a);
                FMA2(s1b, wh1[j + 1], hv[j + 1], s1b);
                FMA2(la,  wr[j],      hv[j],     la);
                FMA2(lb,  wr[j + 1],  hv[j + 1], lb);
            }
            ADD2(s0a, s0a, s0b);
            ADD2(s1a, s1a, s1b);
            ADD2(la,  la,  lb);

            // readout consumed h_{t-1} -> logits for step t-1
            float2 dl = u2f(la);
            const float lg = dl.x + dl.y + bro;
            if (t > 0 && l16 < NA)
                logits[(size_t)(t - 1) * NA + l16] = lg;

            float2 d0 = u2f(s0a);
            float2 d1 = u2f(s1a);
            const float h0 = tanh_scaled(d0.x + d0.y);
            const float h1 = tanh_scaled(d1.x + d1.y);
            *(float2*)&hbuf[np][grp][o0] = make_float2(h0, h1);
        }

        // -------- project next chunk (loads have landed by now) --------
        {
            const float rs[CH] = {nrf.x, nrf.y, nrf.z, nrf.w};
            float4 af[CH] = {naf0, naf1, naf2, naf3};
            #pragma unroll
            for (int i = 0; i < CH; i++) {
                xc0[i] = fmaf(af[i].x, wi0[0], fmaf(af[i].y, wi0[1],
                         fmaf(af[i].z, wi0[2], fmaf(af[i].w, wi0[3],
                         fmaf(rs[i], wi0[4], bias0)))));
                xc1[i] = fmaf(af[i].x, wi1[0], fmaf(af[i].y, wi1[1],
                         fmaf(af[i].z, wi1[2], fmaf(af[i].w, wi1[3],
                         fmaf(rs[i], wi1[4], bias1)))));
            }
        }
    }

    __syncwarp();  // final STS (t=1023 wrote parity buffer 0) visible

    // tail: logits for t = T-1 from h_T
    {
        unsigned long long la = 0, lb = 0;
        const ulonglong2* hp = (const ulonglong2*)hbuf[0][grp];
        #pragma unroll
        for (int j = 0; j < 8; j++) {
            ulonglong2 q = hp[j];
            FMA2(la, wr[2 * j],     q.x, la);
            FMA2(lb, wr[2 * j + 1], q.y, lb);
        }
        ADD2(la, la, lb);
        float2 dl = u2f(la);
        if (l16 < NA)
            logits[(size_t)(TT - 1) * NA + l16] = dl.x + dl.y + bro;
    }

    // final hidden state
    {
        const float2 hfin = *(const float2*)&hbuf[0][grp][o0];
        *(float2*)&hT[o0] = hfin;
    }
}

extern "C" void kernel_launch(void* const* d_in, const int* in_sizes, int n_in,
                              void* d_out, int out_size) {
    const float* act  = (const float*)d_in[0];
    const float* rew  = (const float*)d_in[1];
    const float* W_ih = (const float*)d_in[2];
    const float* W_hh = (const float*)d_in[3];
    const float* b_ih = (const float*)d_in[4];
    const float* b_hh = (const float*)d_in[5];
    const float* W_ro = (const float*)d_in[6];
    const float* b_ro = (const float*)d_in[7];
    float* out = (float*)d_out;

    vanilla_rnn_kernel<<<BB / 2, 32>>>(act, rew, W_ih, W_hh, b_ih, b_hh,
                                       W_ro, b_ro, out);
}

// round 4
// speedup vs baseline: 1.8860x; 1.1452x over previous
#include <cuda_runtime.h>

#define BB 2048
#define TT 1024
#define H  32
#define NA 4
#define CH 8
#define NCH (TT / CH)

typedef unsigned long long u64;

// packed f32x2 ops (sm_103a)
#define FMA2(d, a, b, c) \
    asm("fma.rn.f32x2 %0, %1, %2, %3;" : "=l"(d) : "l"(a), "l"(b), "l"(c))
#define ADD2(d, a, b) \
    asm("add.rn.f32x2 %0, %1, %2;" : "=l"(d) : "l"(a), "l"(b))

static __device__ __forceinline__ u64 f2u(float x, float y) {
    u64 r;
    asm("mov.b64 %0, {%1, %2};" : "=l"(r) : "f"(x), "f"(y));
    return r;
}
static __device__ __forceinline__ float2 u2f(u64 v) {
    float2 r;
    asm("mov.b64 {%0, %1}, %2;" : "=f"(r.x), "=f"(r.y) : "l"(v));
    return r;
}
static __device__ __forceinline__ float tanh_fast(float z) {
    float r;
    asm("tanh.approx.f32 %0, %1;" : "=f"(r) : "f"(z));
    return r;
}

// dot of a 32-float smem row with 16 packed weight pairs
static __device__ __forceinline__ float dot32(const u64* w, const float* hrow) {
    const ulonglong2* hp = (const ulonglong2*)hrow;
    u64 a = 0, b = 0, c = 0, d = 0;
    #pragma unroll
    for (int j = 0; j < 4; j++) {
        ulonglong2 q1 = hp[2 * j];
        ulonglong2 q2 = hp[2 * j + 1];
        FMA2(a, w[4 * j + 0], q1.x, a);
        FMA2(b, w[4 * j + 1], q1.y, b);
        FMA2(c, w[4 * j + 2], q2.x, c);
        FMA2(d, w[4 * j + 3], q2.y, d);
    }
    ADD2(a, a, b);
    ADD2(c, c, d);
    ADD2(a, a, c);
    float2 f = u2f(a);
    return f.x + f.y;
}

__global__ __launch_bounds__(32, 1) void vanilla_rnn_kernel(
    const float* __restrict__ act,   // [B, T, 4]
    const float* __restrict__ rew,   // [B, T, 1]
    const float* __restrict__ W_ih,  // [32, 5]
    const float* __restrict__ W_hh,  // [32, 32]
    const float* __restrict__ b_ih,  // [32]
    const float* __restrict__ b_hh,  // [32]
    const float* __restrict__ W_ro,  // [4, 32]
    const float* __restrict__ b_ro,  // [4]
    float* __restrict__ out)         // [B*T*4 logits][B*32 h_T]
{
    const int lane = threadIdx.x;
    const int grp  = lane >> 4;   // which of the 2 batch rows in this warp
    const int l16  = lane & 15;
    const int b    = blockIdx.x * 2 + grp;

    // 8-slot ring of h vectors, one 40-float padded row per batch row.
    __shared__ __align__(16) float hring[CH][2][40];

    const int o0 = 2 * l16;       // lane owns h[o0], h[o0+1]
    const int o1 = o0 + 1;

    // recurrence weights: rows o0,o1 of W_hh packed over columns
    u64 wh0[16], wh1[16];
    const u64* whh_u = (const u64*)W_hh;
    #pragma unroll
    for (int j = 0; j < 16; j++) {
        wh0[j] = whh_u[o0 * 16 + j];
        wh1[j] = whh_u[o1 * 16 + j];
    }
    // readout: this lane handles action a_act at t_local tl and tl+4
    const int a_act = l16 & 3;
    const int tl    = l16 >> 2;
    u64 wr[16];
    const u64* wro_u = (const u64*)W_ro;
    #pragma unroll
    for (int j = 0; j < 16; j++) wr[j] = wro_u[a_act * 16 + j];
    const float bro = b_ro[a_act];

    // input projection weights, packed as (row o0, row o1)
    u64 wip[5];
    #pragma unroll
    for (int k = 0; k < 5; k++) wip[k] = f2u(W_ih[o0 * 5 + k], W_ih[o1 * 5 + k]);
    const u64 biasp = f2u(b_ih[o0] + b_hh[o0], b_ih[o1] + b_hh[o1]);

    const float4* actv = (const float4*)act + (size_t)b * TT;   // 1 float4/step
    const float4* rewv = (const float4*)(rew + (size_t)b * TT); // 2 float4/block
    float* logits = out + (size_t)b * TT * NA;
    float* hT     = out + (size_t)BB * TT * NA + (size_t)b * H;

    // h_{-1} = 0 lives in slot 7 (step 0 reads slot (0-1)&7)
    *(float2*)&hring[CH - 1][grp][o0] = make_float2(0.0f, 0.0f);

    // ---- prologue: load + project block 0 ----
    u64 xc[CH];
    {
        float4 af[CH];
        #pragma unroll
        for (int i = 0; i < CH; i++) af[i] = __ldg(actv + i);
        const float4 r0 = __ldg(rewv + 0), r1 = __ldg(rewv + 1);
        const float rs[CH] = {r0.x, r0.y, r0.z, r0.w, r1.x, r1.y, r1.z, r1.w};
        #pragma unroll
        for (int i = 0; i < CH; i++) {
            u64 t;
            t = biasp;
            FMA2(t, f2u(rs[i],   rs[i]),   wip[4], t);
            FMA2(t, f2u(af[i].w, af[i].w), wip[3], t);
            FMA2(t, f2u(af[i].z, af[i].z), wip[2], t);
            FMA2(t, f2u(af[i].y, af[i].y), wip[1], t);
            FMA2(t, f2u(af[i].x, af[i].x), wip[0], t);
            xc[i] = t;
        }
    }

    float h0 = 0.0f, h1 = 0.0f;

    #pragma unroll 1
    for (int c = 0; c < NCH; c++) {
        // prefetch next block's inputs (consumed ~8 steps later)
        const int cn = (c + 1 < NCH) ? (c + 1) : (NCH - 1);
        float4 naf[CH];
        #pragma unroll
        for (int i = 0; i < CH; i++) naf[i] = __ldg(actv + cn * CH + i);
        const float4 nr0 = __ldg(rewv + 2 * cn + 0);
        const float4 nr1 = __ldg(rewv + 2 * cn + 1);

        // ---- 8 serial recurrence steps ----
        #pragma unroll
        for (int i = 0; i < CH; i++) {
            __syncwarp();   // previous STS visible to all lanes

            u64 hv[16];
            const ulonglong2* hp = (const ulonglong2*)hring[(i + CH - 1) & (CH - 1)][grp];
            #pragma unroll
            for (int j = 0; j < 8; j++) {
                ulonglong2 q = hp[j];
                hv[2 * j]     = q.x;
                hv[2 * j + 1] = q.y;
            }

            const float2 xp = u2f(xc[i]);
            u64 s0[4], s1[4];
            s0[0] = f2u(xp.x, 0.0f); s0[1] = 0; s0[2] = 0; s0[3] = 0;
            s1[0] = f2u(xp.y, 0.0f); s1[1] = 0; s1[2] = 0; s1[3] = 0;
            #pragma unroll
            for (int q = 0; q < 4; q++) {
                #pragma unroll
                for (int j = 0; j < 4; j++) {
                    FMA2(s0[q], wh0[4 * q + j], hv[4 * q + j], s0[q]);
                    FMA2(s1[q], wh1[4 * q + j], hv[4 * q + j], s1[q]);
                }
            }
            ADD2(s0[0], s0[0], s0[1]);
            ADD2(s0[2], s0[2], s0[3]);
            ADD2(s0[0], s0[0], s0[2]);
            ADD2(s1[0], s1[0], s1[1]);
            ADD2(s1[2], s1[2], s1[3]);
            ADD2(s1[0], s1[0], s1[2]);
            const float2 d0 = u2f(s0[0]);
            const float2 d1 = u2f(s1[0]);
            h0 = tanh_fast(d0.x + d0.y);
            h1 = tanh_fast(d1.x + d1.y);
            *(float2*)&hring[i][grp][o0] = make_float2(h0, h1);
        }

        __syncwarp();   // slot 7's STS visible before readout

        // ---- readout for the 8 finished steps (off the serial chain) ----
        {
            const float lg0 = dot32(wr, hring[tl][grp])     + bro;
            const float lg1 = dot32(wr, hring[tl + 4][grp]) + bro;
            const size_t tb = (size_t)c * CH;
            logits[(tb + tl)     * NA + a_act] = lg0;
            logits[(tb + tl + 4) * NA + a_act] = lg1;
        }

        // ---- project next block (loads have landed) ----
        {
            const float rs[CH] = {nr0.x, nr0.y, nr0.z, nr0.w,
                                  nr1.x, nr1.y, nr1.z, nr1.w};
            #pragma unroll
            for (int i = 0; i < CH; i++) {
                u64 t = biasp;
                FMA2(t, f2u(rs[i],    rs[i]),    wip[4], t);
                FMA2(t, f2u(naf[i].w, naf[i].w), wip[3], t);
                FMA2(t, f2u(naf[i].z, naf[i].z), wip[2], t);
                FMA2(t, f2u(naf[i].y, naf[i].y), wip[1], t);
                FMA2(t, f2u(naf[i].x, naf[i].x), wip[0], t);
                xc[i] = t;
            }
        }
    }

    // final hidden state: this lane's own two elements are still in h0,h1
    *(float2*)&hT[o0] = make_float2(h0, h1);
}

extern "C" void kernel_launch(void* const* d_in, const int* in_sizes, int n_in,
                              void* d_out, int out_size) {
    const float* act  = (const float*)d_in[0];
    const float* rew  = (const float*)d_in[1];
    const float* W_ih = (const float*)d_in[2];
    const float* W_hh = (const float*)d_in[3];
    const float* b_ih = (const float*)d_in[4];
    const float* b_hh = (const float*)d_in[5];
    const float* W_ro = (const float*)d_in[6];
    const float* b_ro = (const float*)d_in[7];
    float* out = (float*)d_out;

    vanilla_rnn_kernel<<<BB / 2, 32>>>(act, rew, W_ih, W_hh, b_ih, b_hh,
                                       W_ro, b_ro, out);
}